// round 2
// baseline (speedup 1.0000x reference)
#include <cuda_runtime.h>

#define NN 100000
#define NE 1600000
#define NG 16
#define PERG (NE / NG)      // 100000 edges per graph segment
#define TSTEP (NN / NG)     // 6250 threshold step
#define BN_EPS 1e-5f
#define FULLMASK 0xffffffffu

// ---------------- scratch (device globals; no allocation allowed) ----------
__device__ float g_acc1[NN * 64];   // x + aggr1 accumulation
__device__ float g_h1[NN * 64];     // MLP1 output (post-relu, pre-BN)
__device__ float g_acc2[NN * 64];   // bn(h1) + aggr2 accumulation
__device__ float g_stats1[128];     // sum[64], sumsq[64] for BN1
__device__ float g_stats2[128];     // sum[64], sumsq[64] for BN2
__device__ float g_ab1[128];        // BN1 folded affine: a[64], b[64]
__device__ float g_gsum[NG * 64];   // per-graph feature sums (pre-BN2)
__device__ float g_cnt[NG];         // per-graph node counts

// ---------------- helpers ---------------------------------------------------
__device__ __forceinline__ void red_add_v4(float4* addr, float4 v) {
    asm volatile("red.global.add.v4.f32 [%0], {%1,%2,%3,%4};"
                 :: "l"(addr), "f"(v.x), "f"(v.y), "f"(v.z), "f"(v.w)
                 : "memory");
}

// ---------------- kernels ---------------------------------------------------
__global__ void zero_kernel() {
    int i = blockIdx.x * blockDim.x + threadIdx.x;
    if (i < 128)            g_stats1[i] = 0.f;
    else if (i < 256)       g_stats2[i - 128] = 0.f;
    else if (i < 256 + NG * 64) g_gsum[i - 256] = 0.f;
    else if (i < 256 + NG * 64 + NG) g_cnt[i - 256 - NG * 64] = 0.f;
}

__global__ void copy_init_kernel(const float4* __restrict__ x) {
    int i = blockIdx.x * blockDim.x + threadIdx.x;
    if (i < NN * 16) ((float4*)g_acc1)[i] = x[i];
}

// layer 0: feat = x, acc = g_acc1, no affine.
// layer 1: feat = g_h1 (BN affine applied inline), acc = g_acc2.
__global__ void scatter_kernel(const int* __restrict__ ei,
                               const float4* __restrict__ xfeat, int layer) {
    int idx = blockIdx.x * blockDim.x + threadIdx.x;
    int e = idx >> 4;
    if (e >= NE) return;
    int c = idx & 15;

    int th = (e / PERG) * TSTEP;
    int s = __ldg(&ei[e]);
    int d = __ldg(&ei[NE + e]);
    if (s < th || d < th) return;

    const float4* feat = (layer == 0) ? xfeat : (const float4*)g_h1;
    float4* acc = (layer == 0) ? (float4*)g_acc1 : (float4*)g_acc2;

    float4 v = __ldg(&feat[s * 16 + c]);
    if (layer == 1) {
        const float4* ab = (const float4*)g_ab1;
        float4 a = __ldg(&ab[c]);
        float4 b = __ldg(&ab[16 + c]);
        v.x = fmaf(v.x, a.x, b.x);
        v.y = fmaf(v.y, a.y, b.y);
        v.z = fmaf(v.z, a.z, b.z);
        v.w = fmaf(v.w, a.w, b.w);
    }
    red_add_v4(&acc[d * 16 + c], v);
}

// MLP1: 64 -> relu 32 -> relu 64, writes g_h1, accumulates BN1 stats.
__global__ __launch_bounds__(256) void mlp1_kernel(
    const float* __restrict__ W1a, const float* __restrict__ b1a,
    const float* __restrict__ W1b, const float* __restrict__ b1b) {
    __shared__ float sWa[64 * 32];
    __shared__ float sWb[32 * 64];
    __shared__ float sba[32];
    __shared__ float sbb[64];
    for (int i = threadIdx.x; i < 64 * 32; i += blockDim.x) {
        sWa[i] = W1a[i];
        sWb[i] = W1b[i];
    }
    if (threadIdx.x < 32) sba[threadIdx.x] = b1a[threadIdx.x];
    if (threadIdx.x < 64) sbb[threadIdx.x] = b1b[threadIdx.x];
    __syncthreads();

    int lane = threadIdx.x & 31;
    int warp = (blockIdx.x * blockDim.x + threadIdx.x) >> 5;
    int nwarps = (gridDim.x * blockDim.x) >> 5;
    int chunk = (NN + nwarps - 1) / nwarps;
    int start = warp * chunk;
    int end = min(start + chunk, NN);

    float s0 = 0.f, s1 = 0.f, q0 = 0.f, q1 = 0.f;
    for (int i = start; i < end; i++) {
        const float* row = g_acc1 + i * 64;
        float r0 = row[lane], r1 = row[lane + 32];
        float t = sba[lane];
#pragma unroll
        for (int k = 0; k < 32; k++)
            t = fmaf(__shfl_sync(FULLMASK, r0, k), sWa[k * 32 + lane], t);
#pragma unroll
        for (int k = 0; k < 32; k++)
            t = fmaf(__shfl_sync(FULLMASK, r1, k), sWa[(k + 32) * 32 + lane], t);
        t = fmaxf(t, 0.f);
        float h0 = sbb[lane], h1 = sbb[lane + 32];
#pragma unroll
        for (int k = 0; k < 32; k++) {
            float tv = __shfl_sync(FULLMASK, t, k);
            h0 = fmaf(tv, sWb[k * 64 + lane], h0);
            h1 = fmaf(tv, sWb[k * 64 + lane + 32], h1);
        }
        h0 = fmaxf(h0, 0.f);
        h1 = fmaxf(h1, 0.f);
        g_h1[i * 64 + lane] = h0;
        g_h1[i * 64 + lane + 32] = h1;
        s0 += h0; s1 += h1; q0 += h0 * h0; q1 += h1 * h1;
    }
    atomicAdd(&g_stats1[lane], s0);
    atomicAdd(&g_stats1[lane + 32], s1);
    atomicAdd(&g_stats1[64 + lane], q0);
    atomicAdd(&g_stats1[96 + lane], q1);
}

// Fold BN1 into affine a,b:  bn(v) = v*a + b
__global__ void finalize1_kernel(const float* __restrict__ gamma,
                                 const float* __restrict__ beta) {
    int f = threadIdx.x;
    float mean = g_stats1[f] * (1.f / NN);
    float var = g_stats1[64 + f] * (1.f / NN) - mean * mean;
    float a = gamma[f] * rsqrtf(var + BN_EPS);
    g_ab1[f] = a;
    g_ab1[64 + f] = beta[f] - mean * a;
}

// acc2 = bn(h1)  (self term for layer-2 GIN)
__global__ void bn_init_kernel() {
    int i = blockIdx.x * blockDim.x + threadIdx.x;
    if (i >= NN * 16) return;
    int c = i & 15;
    const float4* ab = (const float4*)g_ab1;
    float4 a = __ldg(&ab[c]);
    float4 b = __ldg(&ab[16 + c]);
    float4 v = ((const float4*)g_h1)[i];
    v.x = fmaf(v.x, a.x, b.x);
    v.y = fmaf(v.y, a.y, b.y);
    v.z = fmaf(v.z, a.z, b.z);
    v.w = fmaf(v.w, a.w, b.w);
    ((float4*)g_acc2)[i] = v;
}

// MLP2: 64 -> relu 64 -> relu 64; accumulates BN2 stats + per-graph sums/counts.
__global__ __launch_bounds__(256) void mlp2_kernel(
    const float* __restrict__ W2a, const float* __restrict__ b2a,
    const float* __restrict__ W2b, const float* __restrict__ b2b,
    const int* __restrict__ batch) {
    __shared__ float sWa[64 * 64];
    __shared__ float sWb[64 * 64];
    __shared__ float sba[64];
    __shared__ float sbb[64];
    for (int i = threadIdx.x; i < 64 * 64; i += blockDim.x) {
        sWa[i] = W2a[i];
        sWb[i] = W2b[i];
    }
    if (threadIdx.x < 64) {
        sba[threadIdx.x] = b2a[threadIdx.x];
        sbb[threadIdx.x] = b2b[threadIdx.x];
    }
    __syncthreads();

    int lane = threadIdx.x & 31;
    int warp = (blockIdx.x * blockDim.x + threadIdx.x) >> 5;
    int nwarps = (gridDim.x * blockDim.x) >> 5;
    int chunk = (NN + nwarps - 1) / nwarps;
    int start = warp * chunk;
    int end = min(start + chunk, NN);

    float s0 = 0.f, s1 = 0.f, q0 = 0.f, q1 = 0.f;
    float p0 = 0.f, p1 = 0.f, crun = 0.f;
    int cg = -1;

    for (int i = start; i < end; i++) {
        const float* row = g_acc2 + i * 64;
        float r0 = row[lane], r1 = row[lane + 32];
        float t0 = sba[lane], t1 = sba[lane + 32];
#pragma unroll
        for (int k = 0; k < 32; k++) {
            float a = __shfl_sync(FULLMASK, r0, k);
            t0 = fmaf(a, sWa[k * 64 + lane], t0);
            t1 = fmaf(a, sWa[k * 64 + lane + 32], t1);
        }
#pragma unroll
        for (int k = 0; k < 32; k++) {
            float a = __shfl_sync(FULLMASK, r1, k);
            t0 = fmaf(a, sWa[(k + 32) * 64 + lane], t0);
            t1 = fmaf(a, sWa[(k + 32) * 64 + lane + 32], t1);
        }
        t0 = fmaxf(t0, 0.f);
        t1 = fmaxf(t1, 0.f);
        float h0 = sbb[lane], h1 = sbb[lane + 32];
#pragma unroll
        for (int k = 0; k < 32; k++) {
            float a = __shfl_sync(FULLMASK, t0, k);
            h0 = fmaf(a, sWb[k * 64 + lane], h0);
            h1 = fmaf(a, sWb[k * 64 + lane + 32], h1);
        }
#pragma unroll
        for (int k = 0; k < 32; k++) {
            float a = __shfl_sync(FULLMASK, t1, k);
            h0 = fmaf(a, sWb[(k + 32) * 64 + lane], h0);
            h1 = fmaf(a, sWb[(k + 32) * 64 + lane + 32], h1);
        }
        h0 = fmaxf(h0, 0.f);
        h1 = fmaxf(h1, 0.f);
        s0 += h0; s1 += h1; q0 += h0 * h0; q1 += h1 * h1;

        int g = __ldg(&batch[i]);
        if (g != cg) {
            if (cg >= 0) {
                atomicAdd(&g_gsum[cg * 64 + lane], p0);
                atomicAdd(&g_gsum[cg * 64 + lane + 32], p1);
                if (lane == 0) atomicAdd(&g_cnt[cg], crun);
            }
            cg = g; p0 = 0.f; p1 = 0.f; crun = 0.f;
        }
        p0 += h0; p1 += h1; crun += 1.f;
    }
    if (cg >= 0) {
        atomicAdd(&g_gsum[cg * 64 + lane], p0);
        atomicAdd(&g_gsum[cg * 64 + lane + 32], p1);
        if (lane == 0) atomicAdd(&g_cnt[cg], crun);
    }
    atomicAdd(&g_stats2[lane], s0);
    atomicAdd(&g_stats2[lane + 32], s1);
    atomicAdd(&g_stats2[64 + lane], q0);
    atomicAdd(&g_stats2[96 + lane], q1);
}

// out[g][f] = (gsum/cnt - mean2) * invstd2 * gamma2 + beta2
__global__ void finalize2_kernel(const float* __restrict__ gamma,
                                 const float* __restrict__ beta,
                                 float* __restrict__ out) {
    int f = threadIdx.x;   // 64
    int g = blockIdx.x;    // 16
    float mean = g_stats2[f] * (1.f / NN);
    float var = g_stats2[64 + f] * (1.f / NN) - mean * mean;
    float inv = rsqrtf(var + BN_EPS);
    float cnt = fmaxf(g_cnt[g], 1.f);
    float m = g_gsum[g * 64 + f] / cnt;
    out[g * 64 + f] = (m - mean) * inv * gamma[f] + beta[f];
}

// ---------------- launch ----------------------------------------------------
extern "C" void kernel_launch(void* const* d_in, const int* in_sizes, int n_in,
                              void* d_out, int out_size) {
    const float* x = (const float*)d_in[0];
    const int* ei = (const int*)d_in[1];
    const int* batch = (const int*)d_in[2];

    // scalars (num_graphs, num_nodes) may appear as size-1 inputs; skip them.
    int base = 3;
    while (base < n_in && in_sizes[base] == 1) base++;
    const float* W1a = (const float*)d_in[base + 0];
    const float* b1a = (const float*)d_in[base + 1];
    const float* W1b = (const float*)d_in[base + 2];
    const float* b1b = (const float*)d_in[base + 3];
    const float* g1  = (const float*)d_in[base + 4];
    const float* be1 = (const float*)d_in[base + 5];
    const float* W2a = (const float*)d_in[base + 6];
    const float* b2a = (const float*)d_in[base + 7];
    const float* W2b = (const float*)d_in[base + 8];
    const float* b2b = (const float*)d_in[base + 9];
    const float* g2  = (const float*)d_in[base + 10];
    const float* be2 = (const float*)d_in[base + 11];
    float* out = (float*)d_out;

    zero_kernel<<<6, 256>>>();
    copy_init_kernel<<<(NN * 16 + 255) / 256, 256>>>((const float4*)x);
    scatter_kernel<<<NE / 16, 256>>>(ei, (const float4*)x, 0);
    mlp1_kernel<<<512, 256>>>(W1a, b1a, W1b, b1b);
    finalize1_kernel<<<1, 64>>>(g1, be1);
    bn_init_kernel<<<(NN * 16 + 255) / 256, 256>>>();
    scatter_kernel<<<NE / 16, 256>>>(ei, (const float4*)x, 1);
    mlp2_kernel<<<512, 256>>>(W2a, b2a, W2b, b2b, batch);
    finalize2_kernel<<<NG, 64>>>(g2, be2, out);
}

// round 3
// speedup vs baseline: 2.2673x; 2.2673x over previous
#include <cuda_runtime.h>

#define NN 100000
#define NE 1600000
#define NG 16
#define PERG (NE / NG)      // 100000 edges per graph segment
#define TSTEP (NN / NG)     // 6250 threshold step
#define BN_EPS 1e-5f

typedef unsigned long long u64;

// ---------------- scratch ----------------------------------------------------
__device__ float g_acc1[NN * 64];   // x + aggr1
__device__ float g_h1[NN * 64];     // MLP1 output (post-relu, pre-BN)
__device__ float g_acc2[NN * 64];   // bn(h1) + aggr2
__device__ float g_stats1[128];
__device__ float g_stats2[128];
__device__ float g_ab1[128];        // BN1 folded affine
__device__ float g_gsum[NG * 64];
__device__ float g_cnt[NG];

// ---------------- helpers ----------------------------------------------------
__device__ __forceinline__ void red_add_v4(float4* addr, float4 v) {
    asm volatile("red.global.add.v4.f32 [%0], {%1,%2,%3,%4};"
                 :: "l"(addr), "f"(v.x), "f"(v.y), "f"(v.z), "f"(v.w)
                 : "memory");
}
__device__ __forceinline__ u64 pk2(float lo, float hi) {
    u64 r; asm("mov.b64 %0, {%1,%2};" : "=l"(r) : "f"(lo), "f"(hi)); return r;
}
__device__ __forceinline__ void upk2(u64 v, float& a, float& b) {
    asm("mov.b64 {%0,%1}, %2;" : "=f"(a), "=f"(b) : "l"(v));
}
__device__ __forceinline__ u64 ffma2(u64 a, u64 b, u64 c) {
    u64 d; asm("fma.rn.f32x2 %0, %1, %2, %3;" : "=l"(d) : "l"(a), "l"(b), "l"(c));
    return d;
}
__device__ __forceinline__ u64 add2(u64 a, u64 b) {
    u64 d; asm("add.rn.f32x2 %0, %1, %2;" : "=l"(d) : "l"(a), "l"(b));
    return d;
}
__device__ __forceinline__ u64 relu2(u64 v) {
    float a, b; upk2(v, a, b);
    return pk2(fmaxf(a, 0.f), fmaxf(b, 0.f));
}

// ---------------- small kernels ----------------------------------------------
__global__ void zero_kernel() {
    int i = blockIdx.x * blockDim.x + threadIdx.x;
    if (i < 128)            g_stats1[i] = 0.f;
    else if (i < 256)       g_stats2[i - 128] = 0.f;
    else if (i < 256 + NG * 64) g_gsum[i - 256] = 0.f;
    else if (i < 256 + NG * 64 + NG) g_cnt[i - 256 - NG * 64] = 0.f;
}

__global__ void copy_init_kernel(const float4* __restrict__ x) {
    int i = blockIdx.x * blockDim.x + threadIdx.x;
    if (i < NN * 16) ((float4*)g_acc1)[i] = x[i];
}

// layer 0: feat = x -> g_acc1 ; layer 1: feat = g_h1 (BN affine inline) -> g_acc2
__global__ void scatter_kernel(const int* __restrict__ ei,
                               const float4* __restrict__ xfeat, int layer) {
    int idx = blockIdx.x * blockDim.x + threadIdx.x;
    int e = idx >> 4;
    if (e >= NE) return;
    int c = idx & 15;

    int th = (e / PERG) * TSTEP;
    int s = __ldg(&ei[e]);
    int d = __ldg(&ei[NE + e]);
    if (s < th || d < th) return;

    const float4* feat = (layer == 0) ? xfeat : (const float4*)g_h1;
    float4* acc = (layer == 0) ? (float4*)g_acc1 : (float4*)g_acc2;

    float4 v = __ldg(&feat[s * 16 + c]);
    if (layer == 1) {
        const float4* ab = (const float4*)g_ab1;
        float4 a = __ldg(&ab[c]);
        float4 b = __ldg(&ab[16 + c]);
        v.x = fmaf(v.x, a.x, b.x);
        v.y = fmaf(v.y, a.y, b.y);
        v.z = fmaf(v.z, a.z, b.z);
        v.w = fmaf(v.w, a.w, b.w);
    }
    red_add_v4(&acc[d * 16 + c], v);
}

// ---------------- MLP1: 64 -> relu 32 -> relu 64 -----------------------------
// Warp processes groups of 8 nodes (4 node pairs packed into f32x2 lanes).
// smem: Wa_dup[64*32] u64, Wb_dup[32*64] u64, xs[8 warps][64 rows x 6 u64]
__global__ __launch_bounds__(256) void mlp1_kernel(
    const float* __restrict__ W1a, const float* __restrict__ b1a,
    const float* __restrict__ W1b, const float* __restrict__ b1b) {
    extern __shared__ u64 sm[];
    u64* sWa = sm;              // 2048
    u64* sWb = sm + 2048;       // 2048
    u64* xsAll = sm + 4096;     // 8 * 384

    for (int i = threadIdx.x; i < 2048; i += 256) {
        float wa = W1a[i]; sWa[i] = pk2(wa, wa);
        float wb = W1b[i]; sWb[i] = pk2(wb, wb);
    }
    __syncthreads();

    int lane = threadIdx.x & 31;
    u64* xs = xsAll + (threadIdx.x >> 5) * 384;
    float* xsf = (float*)xs;

    int warp = (blockIdx.x * 256 + threadIdx.x) >> 5;
    int nw = (gridDim.x * 256) >> 5;
    int ngroups = NN / 8;
    int chunk = (ngroups + nw - 1) / nw;
    int gBeg = warp * chunk;
    int gEnd = min(gBeg + chunk, ngroups);

    u64 bA;  { float b = b1a[lane];      bA  = pk2(b, b); }
    u64 bbL; { float b = b1b[lane];      bbL = pk2(b, b); }
    u64 bbH; { float b = b1b[lane + 32]; bbH = pk2(b, b); }

    u64 sA = 0, sB = 0, qA = 0, qB = 0;

    for (int g = gBeg; g < gEnd; g++) {
        int nb = g * 8;
        // stage 8 node rows transposed into pair layout: xsf[k*12 + node]
        const float4* src = (const float4*)(g_acc1 + nb * 64);
#pragma unroll
        for (int s = 0; s < 4; s++) {
            int idx = lane + 32 * s;
            int node = idx >> 4, k4 = idx & 15;
            float4 v = src[idx];
            float* p = xsf + k4 * 48 + node;
            p[0] = v.x; p[12] = v.y; p[24] = v.z; p[36] = v.w;
        }
        __syncwarp();

        // layer a: hidden feature = lane (32 hidden)
        u64 A0 = bA, A1 = bA, A2 = bA, A3 = bA;
#pragma unroll 8
        for (int k = 0; k < 64; k++) {
            const ulonglong2* r = (const ulonglong2*)(xs + k * 6);
            ulonglong2 x01 = r[0], x23 = r[1];
            u64 w = sWa[k * 32 + lane];
            A0 = ffma2(x01.x, w, A0); A1 = ffma2(x01.y, w, A1);
            A2 = ffma2(x23.x, w, A2); A3 = ffma2(x23.y, w, A3);
        }
        __syncwarp();
        xs[lane * 6 + 0] = relu2(A0);
        xs[lane * 6 + 1] = relu2(A1);
        xs[lane * 6 + 2] = relu2(A2);
        xs[lane * 6 + 3] = relu2(A3);
        __syncwarp();

        // layer b: out features f = lane and lane+32
        u64 O0 = bbL, O1 = bbL, O2 = bbL, O3 = bbL;
        u64 P0 = bbH, P1 = bbH, P2 = bbH, P3 = bbH;
#pragma unroll 8
        for (int k = 0; k < 32; k++) {
            const ulonglong2* r = (const ulonglong2*)(xs + k * 6);
            ulonglong2 x01 = r[0], x23 = r[1];
            u64 wl = sWb[k * 64 + lane];
            u64 wh = sWb[k * 64 + lane + 32];
            O0 = ffma2(x01.x, wl, O0); O1 = ffma2(x01.y, wl, O1);
            O2 = ffma2(x23.x, wl, O2); O3 = ffma2(x23.y, wl, O3);
            P0 = ffma2(x01.x, wh, P0); P1 = ffma2(x01.y, wh, P1);
            P2 = ffma2(x23.x, wh, P2); P3 = ffma2(x23.y, wh, P3);
        }
        O0 = relu2(O0); O1 = relu2(O1); O2 = relu2(O2); O3 = relu2(O3);
        P0 = relu2(P0); P1 = relu2(P1); P2 = relu2(P2); P3 = relu2(P3);

        u64 O[4] = {O0, O1, O2, O3};
        u64 P[4] = {P0, P1, P2, P3};
#pragma unroll
        for (int p = 0; p < 4; p++) {
            float lo, hi, lo2, hi2;
            upk2(O[p], lo, hi); upk2(P[p], lo2, hi2);
            int n0 = nb + 2 * p;
            g_h1[n0 * 64 + lane] = lo;
            g_h1[(n0 + 1) * 64 + lane] = hi;
            g_h1[n0 * 64 + lane + 32] = lo2;
            g_h1[(n0 + 1) * 64 + lane + 32] = hi2;
            sA = add2(sA, O[p]); qA = ffma2(O[p], O[p], qA);
            sB = add2(sB, P[p]); qB = ffma2(P[p], P[p], qB);
        }
        __syncwarp();
    }

    float a, b;
    upk2(sA, a, b); atomicAdd(&g_stats1[lane], a + b);
    upk2(sB, a, b); atomicAdd(&g_stats1[lane + 32], a + b);
    upk2(qA, a, b); atomicAdd(&g_stats1[64 + lane], a + b);
    upk2(qB, a, b); atomicAdd(&g_stats1[96 + lane], a + b);
}

__global__ void finalize1_kernel(const float* __restrict__ gamma,
                                 const float* __restrict__ beta) {
    int f = threadIdx.x;
    float mean = g_stats1[f] * (1.f / NN);
    float var = g_stats1[64 + f] * (1.f / NN) - mean * mean;
    float a = gamma[f] * rsqrtf(var + BN_EPS);
    g_ab1[f] = a;
    g_ab1[64 + f] = beta[f] - mean * a;
}

__global__ void bn_init_kernel() {
    int i = blockIdx.x * blockDim.x + threadIdx.x;
    if (i >= NN * 16) return;
    int c = i & 15;
    const float4* ab = (const float4*)g_ab1;
    float4 a = __ldg(&ab[c]);
    float4 b = __ldg(&ab[16 + c]);
    float4 v = ((const float4*)g_h1)[i];
    v.x = fmaf(v.x, a.x, b.x);
    v.y = fmaf(v.y, a.y, b.y);
    v.z = fmaf(v.z, a.z, b.z);
    v.w = fmaf(v.w, a.w, b.w);
    ((float4*)g_acc2)[i] = v;
}

// ---------------- MLP2: 64 -> relu 64 -> relu 64 + stats + pooling -----------
__global__ __launch_bounds__(256) void mlp2_kernel(
    const float* __restrict__ W2a, const float* __restrict__ b2a,
    const float* __restrict__ W2b, const float* __restrict__ b2b,
    const int* __restrict__ batch) {
    extern __shared__ u64 sm[];
    u64* sWa = sm;              // 4096
    u64* sWb = sm + 4096;       // 4096
    u64* xsAll = sm + 8192;     // 8 * 384

    for (int i = threadIdx.x; i < 4096; i += 256) {
        float wa = W2a[i]; sWa[i] = pk2(wa, wa);
        float wb = W2b[i]; sWb[i] = pk2(wb, wb);
    }
    __syncthreads();

    int lane = threadIdx.x & 31;
    u64* xs = xsAll + (threadIdx.x >> 5) * 384;
    float* xsf = (float*)xs;

    int warp = (blockIdx.x * 256 + threadIdx.x) >> 5;
    int nw = (gridDim.x * 256) >> 5;
    int ngroups = NN / 8;
    int chunk = (ngroups + nw - 1) / nw;
    int gBeg = warp * chunk;
    int gEnd = min(gBeg + chunk, ngroups);

    u64 baL; { float b = b2a[lane];      baL = pk2(b, b); }
    u64 baH; { float b = b2a[lane + 32]; baH = pk2(b, b); }
    u64 bbL; { float b = b2b[lane];      bbL = pk2(b, b); }
    u64 bbH; { float b = b2b[lane + 32]; bbH = pk2(b, b); }

    u64 sA = 0, sB = 0, qA = 0, qB = 0;
    u64 pA = 0, pB = 0;
    float crun = 0.f;
    int cg = -1;

    for (int g = gBeg; g < gEnd; g++) {
        int nb = g * 8;
        const float4* src = (const float4*)(g_acc2 + nb * 64);
#pragma unroll
        for (int s = 0; s < 4; s++) {
            int idx = lane + 32 * s;
            int node = idx >> 4, k4 = idx & 15;
            float4 v = src[idx];
            float* p = xsf + k4 * 48 + node;
            p[0] = v.x; p[12] = v.y; p[24] = v.z; p[36] = v.w;
        }
        __syncwarp();

        // layer a: hidden f = lane, lane+32
        u64 A0 = baL, A1 = baL, A2 = baL, A3 = baL;
        u64 B0 = baH, B1 = baH, B2 = baH, B3 = baH;
#pragma unroll 8
        for (int k = 0; k < 64; k++) {
            const ulonglong2* r = (const ulonglong2*)(xs + k * 6);
            ulonglong2 x01 = r[0], x23 = r[1];
            u64 wl = sWa[k * 64 + lane];
            u64 wh = sWa[k * 64 + lane + 32];
            A0 = ffma2(x01.x, wl, A0); A1 = ffma2(x01.y, wl, A1);
            A2 = ffma2(x23.x, wl, A2); A3 = ffma2(x23.y, wl, A3);
            B0 = ffma2(x01.x, wh, B0); B1 = ffma2(x01.y, wh, B1);
            B2 = ffma2(x23.x, wh, B2); B3 = ffma2(x23.y, wh, B3);
        }
        __syncwarp();
        xs[lane * 6 + 0] = relu2(A0);
        xs[lane * 6 + 1] = relu2(A1);
        xs[lane * 6 + 2] = relu2(A2);
        xs[lane * 6 + 3] = relu2(A3);
        xs[(lane + 32) * 6 + 0] = relu2(B0);
        xs[(lane + 32) * 6 + 1] = relu2(B1);
        xs[(lane + 32) * 6 + 2] = relu2(B2);
        xs[(lane + 32) * 6 + 3] = relu2(B3);
        __syncwarp();

        // layer b
        u64 O0 = bbL, O1 = bbL, O2 = bbL, O3 = bbL;
        u64 P0 = bbH, P1 = bbH, P2 = bbH, P3 = bbH;
#pragma unroll 8
        for (int k = 0; k < 64; k++) {
            const ulonglong2* r = (const ulonglong2*)(xs + k * 6);
            ulonglong2 x01 = r[0], x23 = r[1];
            u64 wl = sWb[k * 64 + lane];
            u64 wh = sWb[k * 64 + lane + 32];
            O0 = ffma2(x01.x, wl, O0); O1 = ffma2(x01.y, wl, O1);
            O2 = ffma2(x23.x, wl, O2); O3 = ffma2(x23.y, wl, O3);
            P0 = ffma2(x01.x, wh, P0); P1 = ffma2(x01.y, wh, P1);
            P2 = ffma2(x23.x, wh, P2); P3 = ffma2(x23.y, wh, P3);
        }
        u64 O[4] = {relu2(O0), relu2(O1), relu2(O2), relu2(O3)};
        u64 P[4] = {relu2(P0), relu2(P1), relu2(P2), relu2(P3)};

#pragma unroll
        for (int p = 0; p < 4; p++) {
            sA = add2(sA, O[p]); qA = ffma2(O[p], O[p], qA);
            sB = add2(sB, P[p]); qB = ffma2(P[p], P[p], qB);

            int2 bp = ((const int2*)batch)[(nb >> 1) + p];
            if (bp.x == cg && bp.y == cg) {
                pA = add2(pA, O[p]); pB = add2(pB, P[p]); crun += 2.f;
            } else {
                if (cg >= 0 && crun > 0.f) {
                    float a, b;
                    upk2(pA, a, b); atomicAdd(&g_gsum[cg * 64 + lane], a + b);
                    upk2(pB, a, b); atomicAdd(&g_gsum[cg * 64 + lane + 32], a + b);
                    if (lane == 0) atomicAdd(&g_cnt[cg], crun);
                }
                if (bp.x == bp.y) {
                    cg = bp.x; pA = O[p]; pB = P[p]; crun = 2.f;
                } else {
                    float a, b;
                    upk2(O[p], a, b);
                    atomicAdd(&g_gsum[bp.x * 64 + lane], a);
                    u64 tA = pk2(0.f, b);
                    upk2(P[p], a, b);
                    atomicAdd(&g_gsum[bp.x * 64 + lane + 32], a);
                    if (lane == 0) atomicAdd(&g_cnt[bp.x], 1.f);
                    cg = bp.y; pA = tA; pB = pk2(0.f, b); crun = 1.f;
                }
            }
        }
        __syncwarp();
    }
    if (cg >= 0 && crun > 0.f) {
        float a, b;
        upk2(pA, a, b); atomicAdd(&g_gsum[cg * 64 + lane], a + b);
        upk2(pB, a, b); atomicAdd(&g_gsum[cg * 64 + lane + 32], a + b);
        if (lane == 0) atomicAdd(&g_cnt[cg], crun);
    }
    float a, b;
    upk2(sA, a, b); atomicAdd(&g_stats2[lane], a + b);
    upk2(sB, a, b); atomicAdd(&g_stats2[lane + 32], a + b);
    upk2(qA, a, b); atomicAdd(&g_stats2[64 + lane], a + b);
    upk2(qB, a, b); atomicAdd(&g_stats2[96 + lane], a + b);
}

__global__ void finalize2_kernel(const float* __restrict__ gamma,
                                 const float* __restrict__ beta,
                                 float* __restrict__ out) {
    int f = threadIdx.x;
    int g = blockIdx.x;
    float mean = g_stats2[f] * (1.f / NN);
    float var = g_stats2[64 + f] * (1.f / NN) - mean * mean;
    float inv = rsqrtf(var + BN_EPS);
    float cnt = fmaxf(g_cnt[g], 1.f);
    float m = g_gsum[g * 64 + f] / cnt;
    out[g * 64 + f] = (m - mean) * inv * gamma[f] + beta[f];
}

// ---------------- launch -----------------------------------------------------
extern "C" void kernel_launch(void* const* d_in, const int* in_sizes, int n_in,
                              void* d_out, int out_size) {
    const float* x = (const float*)d_in[0];
    const int* ei = (const int*)d_in[1];
    const int* batch = (const int*)d_in[2];

    int base = 3;
    while (base < n_in && in_sizes[base] == 1) base++;
    const float* W1a = (const float*)d_in[base + 0];
    const float* b1a = (const float*)d_in[base + 1];
    const float* W1b = (const float*)d_in[base + 2];
    const float* b1b = (const float*)d_in[base + 3];
    const float* g1  = (const float*)d_in[base + 4];
    const float* be1 = (const float*)d_in[base + 5];
    const float* W2a = (const float*)d_in[base + 6];
    const float* b2a = (const float*)d_in[base + 7];
    const float* W2b = (const float*)d_in[base + 8];
    const float* b2b = (const float*)d_in[base + 9];
    const float* g2  = (const float*)d_in[base + 10];
    const float* be2 = (const float*)d_in[base + 11];
    float* out = (float*)d_out;

    const int smem1 = (2048 + 2048 + 8 * 384) * 8;   // 57344
    const int smem2 = (4096 + 4096 + 8 * 384) * 8;   // 90112
    cudaFuncSetAttribute(mlp1_kernel, cudaFuncAttributeMaxDynamicSharedMemorySize, smem1);
    cudaFuncSetAttribute(mlp2_kernel, cudaFuncAttributeMaxDynamicSharedMemorySize, smem2);

    zero_kernel<<<6, 256>>>();
    copy_init_kernel<<<(NN * 16 + 255) / 256, 256>>>((const float4*)x);
    scatter_kernel<<<NE / 16, 256>>>(ei, (const float4*)x, 0);
    mlp1_kernel<<<592, 256, smem1>>>(W1a, b1a, W1b, b1b);
    finalize1_kernel<<<1, 64>>>(g1, be1);
    bn_init_kernel<<<(NN * 16 + 255) / 256, 256>>>();
    scatter_kernel<<<NE / 16, 256>>>(ei, (const float4*)x, 1);
    mlp2_kernel<<<296, 256, smem2>>>(W2a, b2a, W2b, b2b, batch);
    finalize2_kernel<<<NG, 64>>>(g2, be2, out);
}